// round 15
// baseline (speedup 1.0000x reference)
#include <cuda_runtime.h>
#include <math.h>

// Hyperbolic conv constants (must match reference)
#define CC    0.05f
#define SQC   0.22360679774997896f          // sqrt(0.05)
#define MINN  1e-15f
#define MAXN  (0.996f / SQC)                // (1 - 4e-3)/sqrt(c)
#define MAXN2 (MAXN * MAXN)

typedef unsigned long long u64;

// u tile stride padded to 68 floats (272B) so every row is 16B aligned
#define TW    68
#define TSZ   (66 * TW)                     // 4488 floats per tile
#define TSZ4  (TSZ / 4)                     // 1122 float4
#define TILEB (TSZ * 4)                     // 17952 bytes per tile

// Scratch: u = logmap0(pad(x)), [b][j][66*68], 32*64*4488 floats (~36.8MB)
__device__ float g_u[9191424];
__device__ float g_bh[128];                 // expmap0(bias)

// ---------------------------------------------------------------------------
// packed f32x2 + fast-approx + cp.async helpers
// ---------------------------------------------------------------------------
__device__ __forceinline__ u64 pk(float a, float b) {
    u64 r;
    asm("mov.b64 %0, {%1, %2};" : "=l"(r)
        : "r"(__float_as_uint(a)), "r"(__float_as_uint(b)));
    return r;
}
__device__ __forceinline__ float2 unpk(u64 v) {
    unsigned lo, hi;
    asm("mov.b64 {%0, %1}, %2;" : "=r"(lo), "=r"(hi) : "l"(v));
    return make_float2(__uint_as_float(lo), __uint_as_float(hi));
}
__device__ __forceinline__ u64 fma2(u64 a, u64 b, u64 c) {
    u64 d;
    asm("fma.rn.f32x2 %0, %1, %2, %3;" : "=l"(d) : "l"(a), "l"(b), "l"(c));
    return d;
}
__device__ __forceinline__ float fexp2(float x){ float r; asm("ex2.approx.f32 %0, %1;" : "=f"(r) : "f"(x)); return r; }
__device__ __forceinline__ float frcp (float x){ float r; asm("rcp.approx.f32 %0, %1;" : "=f"(r) : "f"(x)); return r; }
__device__ __forceinline__ float frsq (float x){ float r; asm("rsqrt.approx.f32 %0, %1;" : "=f"(r) : "f"(x)); return r; }

__device__ __forceinline__ void cpasync16(unsigned saddr, const void* g) {
    asm volatile("cp.async.cg.shared.global [%0], [%1], 16;" :: "r"(saddr), "l"(g));
}
#define CP_COMMIT() asm volatile("cp.async.commit_group;")
#define CP_WAIT0()  asm volatile("cp.async.wait_group 0;")

__device__ __forceinline__ float artanhc(float z) {
    z = fminf(z, 1.0f - 1e-7f);             // z >= 0 always here
    return 0.5f * (log1pf(z) - log1pf(-z));
}

// ---------------------------------------------------------------------------
// Kernel 1: u = logmap0(pad(x)) per (b, cin) row (precise), stride-68 layout.
// Block 2048 additionally computes b_h = expmap0(bias).
// ---------------------------------------------------------------------------
__global__ __launch_bounds__(256) void u_kernel(const float* __restrict__ x,
                                                const float* __restrict__ bias) {
    int row = blockIdx.x;
    int t = threadIdx.x;

    if (row == 2048) {                      // bias block
        if (t < 128) {
            float v = bias[t];
            float p = v * v;
            #pragma unroll
            for (int o = 16; o > 0; o >>= 1) p += __shfl_xor_sync(0xffffffffu, p, o);
            __shared__ float smb[4];
            if ((t & 31) == 0) smb[t >> 5] = p;
            __syncwarp();
            asm volatile("bar.sync 1, 128;");
            float s2 = smb[0] + smb[1] + smb[2] + smb[3];
            float bn = fmaxf(sqrtf(s2), MINN);
            float z  = SQC * bn;
            g_bh[t] = tanhf(z) / z * v;
        }
        return;
    }

    const float* xr = x + (size_t)row * 4096;

    float p = 0.0f;
    #pragma unroll
    for (int k = 0; k < 16; k++) { float v = xr[t + (k << 8)]; p += v * v; }
    #pragma unroll
    for (int o = 16; o > 0; o >>= 1) p += __shfl_xor_sync(0xffffffffu, p, o);
    __shared__ float sm[8];
    __shared__ float s_scale;
    if ((t & 31) == 0) sm[t >> 5] = p;
    __syncthreads();
    if (t == 0) {
        float s2 = 0.0f;
        #pragma unroll
        for (int i = 0; i < 8; i++) s2 += sm[i];
        float yn = fmaxf(sqrtf(s2), MINN);
        float z  = SQC * yn;
        s_scale  = artanhc(z) / z;
    }
    __syncthreads();
    float sc = s_scale;

    float* ur = g_u + (size_t)row * TSZ;
    for (int idx = t; idx < TSZ; idx += 256) {
        int r = idx / TW, c = idx - r * TW;
        float v = 0.0f;
        if (r >= 1 && r <= 64 && c >= 1 && c <= 64)
            v = xr[(r - 1) * 64 + (c - 1)] * sc;
        ur[idx] = v;
    }
}

// ---------------------------------------------------------------------------
// Mobius scan scalar math — short chain (no sqrt on common path).
// acc = P*q;  qv = <q,v>.  Returns (sA, sBt); updates a2 = |acc'|^2.
// ---------------------------------------------------------------------------
__device__ __forceinline__ float2 step_scalars(float sv2, float qv, float P, float& a2) {
    float z2 = CC * sv2;                           // z^2
    float tau;
    if (z2 < 0.0625f) {                            // z < 0.25 (always, this data)
        tau = 1.0f + z2 * (-0.33333334f + z2 * (0.13333334f - z2 * 0.053968254f));
    } else {
        float vn = sv2 * frsq(fmaxf(sv2, 1e-28f));
        float z  = SQC * vn;
        float t  = fexp2(z * 2.8853901f);          // e^{2z}
        tau = (t - 1.0f) * frcp((t + 1.0f) * z);
    }
    float tn2 = tau * tau * sv2;                   // |t|^2 before project
    float ts  = tau;
    if (tn2 > MAXN2) ts = tau * (MAXN * frsq(tn2));  // project(t), rare
    float y2  = ts * ts * sv2;
    float xy  = ts * (P * qv);
    float x2  = a2;
    float A   = 1.0f + 2.0f * CC * xy + CC * y2;
    float B   = 1.0f - CC * x2;
    float den = fmaxf(1.0f + 2.0f * CC * xy + CC * CC * x2 * y2, MINN);
    float inv = frcp(den);
    float n2  = (A * A * x2 + 2.0f * A * B * xy + B * B * y2) * (inv * inv);
    float ps  = 1.0f;
    if (n2 > MAXN2) ps = MAXN * frsq(fmaxf(n2, 1e-28f));  // project(acc'), rare
    a2 = ps * ps * n2;
    return make_float2(A * inv * ps, B * inv * ps * ts);
}

__device__ __forceinline__ float2 final_scalars(float sacc, float a2, float bh) {
    float y2  = 4096.0f * bh * bh;
    float xy  = bh * sacc;
    float x2  = a2;
    float A   = 1.0f + 2.0f * CC * xy + CC * y2;
    float B   = 1.0f - CC * x2;
    float den = fmaxf(1.0f + 2.0f * CC * xy + CC * CC * x2 * y2, MINN);
    float inv = frcp(den);
    float n2  = (A * A * x2 + 2.0f * A * B * xy + B * B * y2) * (inv * inv);
    float ps  = 1.0f;
    if (n2 > MAXN2) ps = MAXN * frsq(fmaxf(n2, 1e-28f));
    return make_float2(A * inv * ps, B * inv * ps * bh);
}

// load one 6-wide window row (16B-aligned) as 5 overlapping f32x2 pairs
__device__ __forceinline__ void loadrow(const float* p, u64* row) {
    float4 a = *(const float4*)p;           // floats 0-3 (LDS.128)
    float2 b = *(const float2*)(p + 4);     // floats 4-5 (LDS.64)
    row[0] = pk(a.x, a.y);
    row[1] = pk(a.y, a.z);
    row[2] = pk(a.z, a.w);
    row[3] = pk(a.w, b.x);
    row[4] = pk(b.x, b.y);
}

// row-streaming conv of one tile into v[8] (16 outputs, packed pairs)
__device__ __forceinline__ void conv_tile(const float* basep, const u64* wp, u64* v) {
    #pragma unroll
    for (int i = 0; i < 8; i++) v[i] = 0ull;
    #pragma unroll
    for (int dr = 0; dr < 6; dr++) {
        u64 row[5];
        loadrow(basep + dr * TW, row);
        const int orlo = (dr - 2 > 0) ? dr - 2 : 0;
        const int orhi = (dr < 3) ? dr : 3;
        #pragma unroll
        for (int orow = orlo; orow <= orhi; orow++) {
            const int r = dr - orow;
            #pragma unroll
            for (int k = 0; k < 3; k++) {
                u64 wa = wp[r * 3 + k];
                v[orow * 2]     = fma2(row[k],     wa, v[orow * 2]);
                v[orow * 2 + 1] = fma2(row[2 + k], wa, v[orow * 2 + 1]);
            }
        }
    }
}

// ---------------------------------------------------------------------------
// Kernel 2: one CTA per (b, channel pair), 512 threads — threads 0-255 own
// channel c0, threads 256-511 own c0+1 (tile smem shared by both halves).
// DOUBLE-STEP scan: two input channels per barrier. One block reduction
// yields (|va|^2, |vb|^2, <q,va>, <q,vb>, <va,vb>); both Mobius steps then
// run back-to-back using <q_a,vb> = <q,vb> + qc_a*<va,vb>. 4 rotating tile
// buffers in dynamic smem, prefetched via cp.async at the top of each step.
// ---------------------------------------------------------------------------
__global__ __launch_bounds__(512, 1)
void main_kernel(const float* __restrict__ w, float* __restrict__ out) {
    const int b    = blockIdx.y;
    const int c0   = blockIdx.x * 2;
    const int t    = threadIdx.x;
    const int half = t >> 8;            // my output channel (0/1 within pair)
    const int tid  = t & 255;
    const int ty   = tid >> 4;
    const int tx   = tid & 15;
    const int lane = t & 31;
    const int wid  = (t >> 5) & 7;      // warp within half

    extern __shared__ float su[];       // 4 tile buffers (4*17952B dynamic)
    __shared__ u64   swp[2][576];       // weights pre-duplicated (w,w)
    __shared__ float sred[2][2][8][8];  // [buf][half][warp][slot0-4 (+pad)]
    __shared__ float sepi[2][8];

    for (int i = t; i < 1152; i += 512) {
        int cc = i / 576, rem = i - cc * 576;
        float wv = w[(size_t)(c0 + cc) * 576 + rem];
        swp[cc][rem] = pk(wv, wv);
    }

    const unsigned su_s = (unsigned)__cvta_generic_to_shared(su);
    const float4* gbase = (const float4*)(g_u + (size_t)(b * 64) * TSZ);

    // preload tiles 0,1 into buf0,buf1
    #pragma unroll
    for (int k = 0; k < 3; k++) {
        int i = t + (k << 9);
        if (i < TSZ4) {
            cpasync16(su_s + 0 * TILEB + i * 16, gbase + 0 * TSZ4 + i);
            cpasync16(su_s + 1 * TILEB + i * 16, gbase + 1 * TSZ4 + i);
        }
    }
    CP_COMMIT();
    CP_WAIT0();
    __syncthreads();

    u64 q[8];                           // acc = P * q, packed col pairs
    #pragma unroll
    for (int i = 0; i < 8; i++) q[i] = 0ull;
    float a2m = 0.0f, Pm = 1.0f;

    const int baseoff = (4 * ty) * TW + 4 * tx;

    for (int J = 0; J < 32; J++) {
        const int cur  = J & 1;
        const int bufA = (J & 1) ? 2 : 0;
        const int bufB = bufA + 1;

        // ---- prefetch tiles 2J+2, 2J+3 into the buffers freed last step ----
        {
            const float4* gA = gbase + (size_t)((2 * J + 2) & 63) * TSZ4;
            const float4* gB = gbase + (size_t)((2 * J + 3) & 63) * TSZ4;
            unsigned sA = su_s + (bufA ^ 2) * TILEB;
            unsigned sB = su_s + (bufB ^ 2) * TILEB;
            #pragma unroll
            for (int k = 0; k < 3; k++) {
                int i = t + (k << 9);
                if (i < TSZ4) {
                    cpasync16(sA + i * 16, gA + i);
                    cpasync16(sB + i * 16, gB + i);
                }
            }
            CP_COMMIT();
        }

        // ---- conv both tiles for MY channel ----
        u64 va[8], vb[8];
        conv_tile(su + bufA * TSZ + baseoff, &swp[half][(2 * J) * 9],     va);
        conv_tile(su + bufB * TSZ + baseoff, &swp[half][(2 * J + 1) * 9], vb);

        // ---- fused packed reductions: 5 scalars ----
        u64 rsa = 0ull, rsb = 0ull, rda = 0ull, rdb = 0ull, rx = 0ull;
        #pragma unroll
        for (int i = 0; i < 8; i++) {
            rsa = fma2(va[i], va[i], rsa);
            rsb = fma2(vb[i], vb[i], rsb);
            rda = fma2(q[i],  va[i], rda);
            rdb = fma2(q[i],  vb[i], rdb);
            rx  = fma2(va[i], vb[i], rx);
        }
        float2 ua = unpk(rsa), ub = unpk(rsb), uc = unpk(rda), ud = unpk(rdb), ue = unpk(rx);
        float t_sa = ua.x + ua.y, t_sb = ub.x + ub.y;
        float t_da = uc.x + uc.y, t_db = ud.x + ud.y;
        float t_x  = ue.x + ue.y;

        // ---- warp reduce-scatter: 4 values via split, x via butterfly ----
        const bool b0 = (lane & 1), b1 = (lane & 2);
        float k1 = b0 ? t_sb : t_sa, o1 = b0 ? t_sa : t_sb;
        k1 += __shfl_xor_sync(0xffffffffu, o1, 1);
        float k2 = b0 ? t_db : t_da, o2 = b0 ? t_da : t_db;
        k2 += __shfl_xor_sync(0xffffffffu, o2, 1);
        float K  = b1 ? k2 : k1,     oK = b1 ? k1 : k2;
        K += __shfl_xor_sync(0xffffffffu, oK, 2);
        K += __shfl_xor_sync(0xffffffffu, K, 4);
        K += __shfl_xor_sync(0xffffffffu, K, 8);
        K += __shfl_xor_sync(0xffffffffu, K, 16);
        #pragma unroll
        for (int o = 1; o <= 16; o <<= 1)
            t_x += __shfl_xor_sync(0xffffffffu, t_x, o);
        // lane0:Sa lane1:Sb lane2:Da lane3:Db
        if (lane < 4) sred[cur][half][wid][lane] = K;
        if (lane == 0) sred[cur][half][wid][4] = t_x;

        // prefetch must land before the barrier publishes the buffers
        CP_WAIT0();
        __syncthreads();                  // ONE barrier per TWO input channels

        // ---- tree-sum the 8 warp partials of MY half ----
        float Sa = 0.f, Sb = 0.f, Da = 0.f, Db = 0.f, X = 0.f;
        #pragma unroll
        for (int w2 = 0; w2 < 8; w2++) {
            float4 v4 = *(const float4*)&sred[cur][half][w2][0];
            Sa += v4.x; Sb += v4.y; Da += v4.z; Db += v4.w;
            X  += sred[cur][half][w2][4];
        }

        // ---- two Mobius steps back-to-back (redundant per thread) ----
        float2 s1 = step_scalars(Sa, Da, Pm, a2m);
        Pm *= s1.x;
        float qca = s1.y * frcp(Pm);
        float2 s2 = step_scalars(Sb, Db + qca * X, Pm, a2m);
        Pm *= s2.x;
        float qcb = s2.y * frcp(Pm);
        u64 QA = pk(qca, qca), QB = pk(qcb, qcb);
        #pragma unroll
        for (int i = 0; i < 8; i++) {
            q[i] = fma2(QA, va[i], q[i]);
            q[i] = fma2(QB, vb[i], q[i]);
        }
    }

    // ---- epilogue: mobius bias add + project (acc = P*q) ----
    float sa = 0.0f;
    #pragma unroll
    for (int i = 0; i < 8; i++) {
        float2 p0 = unpk(q[i]); sa += p0.x + p0.y;
    }
    #pragma unroll
    for (int o = 16; o > 0; o >>= 1)
        sa += __shfl_xor_sync(0xffffffffu, sa, o);
    if (lane == 0) sepi[half][wid] = sa;
    __syncthreads();
    float tm = ((sepi[half][0] + sepi[half][1]) + (sepi[half][2] + sepi[half][3]))
             + ((sepi[half][4] + sepi[half][5]) + (sepi[half][6] + sepi[half][7]));

    float2 f = final_scalars(Pm * tm, a2m, g_bh[c0 + half]);
    float fx = f.x * Pm;
    u64 FA = pk(fx, fx), FB = pk(f.y, f.y);

    u64* o0 = (u64*)(out + ((size_t)(b * 128 + c0 + half)) * 4096);
    #pragma unroll
    for (int orow = 0; orow < 4; orow++) {
        #pragma unroll
        for (int p = 0; p < 2; p++) {
            int pos = (4 * ty + orow) * 32 + 2 * tx + p;   // in float2 units
            o0[pos] = fma2(FA, q[orow * 2 + p], FB);
        }
    }
}

// ---------------------------------------------------------------------------
extern "C" void kernel_launch(void* const* d_in, const int* in_sizes, int n_in,
                              void* d_out, int out_size) {
    const float* x    = (const float*)d_in[0];   // [32,64,64,64]
    const float* wgt  = (const float*)d_in[1];   // [128,64,3,3]
    const float* bias = (const float*)d_in[2];   // [128]
    float* out = (float*)d_out;                  // [32,128,64,64]

    // opt-in for >48KB dynamic smem (host-side attribute, not a stream op)
    static int smem_set = 0;
    if (!smem_set) {
        cudaFuncSetAttribute(main_kernel,
                             cudaFuncAttributeMaxDynamicSharedMemorySize,
                             4 * TILEB);
        smem_set = 1;
    }

    u_kernel<<<2049, 256>>>(x, bias);            // block 2048 also does bias
    dim3 grid(64, 32);                           // (cout/2, bs)
    main_kernel<<<grid, 512, 4 * TILEB>>>(wgt, out);
}

// round 16
// speedup vs baseline: 1.3352x; 1.3352x over previous
#include <cuda_runtime.h>
#include <math.h>

// Hyperbolic conv constants (must match reference)
#define CC    0.05f
#define SQC   0.22360679774997896f          // sqrt(0.05)
#define MINN  1e-15f
#define MAXN  (0.996f / SQC)                // (1 - 4e-3)/sqrt(c)
#define MAXN2 (MAXN * MAXN)

typedef unsigned long long u64;

// u tile stride padded to 68 floats (272B) so every row is 16B aligned
#define TW    68
#define TSZ   (66 * TW)                     // 4488 floats per copy
#define PSZ   (2 * TSZ)                     // tile pair (copy A + shifted copy B)
#define PSZ4  (PSZ / 4)                     // 2244 float4 per tile pair
#define PAIRB (PSZ * 4)                     // 35904 bytes per tile pair

// Scratch: u tile pairs [b][j][A:66x68][B:66x68], ~73.5MB
__device__ float g_u[18382848];
__device__ float g_bh[128];                 // expmap0(bias)

// ---------------------------------------------------------------------------
// packed f32x2 + fast-approx + cp.async helpers
// ---------------------------------------------------------------------------
__device__ __forceinline__ u64 pk(float a, float b) {
    u64 r;
    asm("mov.b64 %0, {%1, %2};" : "=l"(r)
        : "r"(__float_as_uint(a)), "r"(__float_as_uint(b)));
    return r;
}
__device__ __forceinline__ float2 unpk(u64 v) {
    unsigned lo, hi;
    asm("mov.b64 {%0, %1}, %2;" : "=r"(lo), "=r"(hi) : "l"(v));
    return make_float2(__uint_as_float(lo), __uint_as_float(hi));
}
__device__ __forceinline__ u64 fma2(u64 a, u64 b, u64 c) {
    u64 d;
    asm("fma.rn.f32x2 %0, %1, %2, %3;" : "=l"(d) : "l"(a), "l"(b), "l"(c));
    return d;
}
__device__ __forceinline__ float fexp2(float x){ float r; asm("ex2.approx.f32 %0, %1;" : "=f"(r) : "f"(x)); return r; }
__device__ __forceinline__ float frcp (float x){ float r; asm("rcp.approx.f32 %0, %1;" : "=f"(r) : "f"(x)); return r; }
__device__ __forceinline__ float frsq (float x){ float r; asm("rsqrt.approx.f32 %0, %1;" : "=f"(r) : "f"(x)); return r; }

__device__ __forceinline__ void cpasync16(unsigned saddr, const void* g) {
    asm volatile("cp.async.cg.shared.global [%0], [%1], 16;" :: "r"(saddr), "l"(g));
}
#define CP_COMMIT() asm volatile("cp.async.commit_group;")
#define CP_WAIT0()  asm volatile("cp.async.wait_group 0;")

__device__ __forceinline__ float artanhc(float z) {
    z = fminf(z, 1.0f - 1e-7f);             // z >= 0 always here
    return 0.5f * (log1pf(z) - log1pf(-z));
}

// ---------------------------------------------------------------------------
// Kernel 1: u = logmap0(pad(x)) per (b, cin) row, writing BOTH copies:
// A[c] = u[c], B[c] = u[c+1] (one-float shift for MOV-free pair loads).
// Block 2048 additionally computes b_h = expmap0(bias).
// ---------------------------------------------------------------------------
__global__ __launch_bounds__(256) void u_kernel(const float* __restrict__ x,
                                                const float* __restrict__ bias) {
    int row = blockIdx.x;
    int t = threadIdx.x;

    if (row == 2048) {                      // bias block
        if (t < 128) {
            float v = bias[t];
            float p = v * v;
            #pragma unroll
            for (int o = 16; o > 0; o >>= 1) p += __shfl_xor_sync(0xffffffffu, p, o);
            __shared__ float smb[4];
            if ((t & 31) == 0) smb[t >> 5] = p;
            __syncwarp();
            asm volatile("bar.sync 1, 128;");
            float s2 = smb[0] + smb[1] + smb[2] + smb[3];
            float bn = fmaxf(sqrtf(s2), MINN);
            float z  = SQC * bn;
            g_bh[t] = tanhf(z) / z * v;
        }
        return;
    }

    const float* xr = x + (size_t)row * 4096;

    float p = 0.0f;
    #pragma unroll
    for (int k = 0; k < 16; k++) { float v = xr[t + (k << 8)]; p += v * v; }
    #pragma unroll
    for (int o = 16; o > 0; o >>= 1) p += __shfl_xor_sync(0xffffffffu, p, o);
    __shared__ float sm[8];
    __shared__ float s_scale;
    if ((t & 31) == 0) sm[t >> 5] = p;
    __syncthreads();
    if (t == 0) {
        float s2 = 0.0f;
        #pragma unroll
        for (int i = 0; i < 8; i++) s2 += sm[i];
        float yn = fmaxf(sqrtf(s2), MINN);
        float z  = SQC * yn;
        s_scale  = artanhc(z) / z;
    }
    __syncthreads();
    float sc = s_scale;

    float* ur = g_u + (size_t)row * PSZ;    // copy A at +0, copy B at +TSZ
    for (int idx = t; idx < TSZ; idx += 256) {
        int r = idx / TW, c = idx - r * TW;
        float va = 0.0f, vb = 0.0f;
        if (r >= 1 && r <= 64) {
            if (c >= 1 && c <= 64) va = xr[(r - 1) * 64 + (c - 1)] * sc;
            if (c <= 63)          vb = xr[(r - 1) * 64 + c] * sc;   // u[r][c+1]
        }
        ur[idx]       = va;
        ur[TSZ + idx] = vb;
    }
}

// ---------------------------------------------------------------------------
// Mobius scan scalar math — short chain (no sqrt on common path).
// acc = P*q;  qv = <q,v>.  Returns (sA, sBt); updates a2 = |acc'|^2.
// ---------------------------------------------------------------------------
__device__ __forceinline__ float2 step_scalars(float sv2, float qv, float P, float& a2) {
    float z2 = CC * sv2;                           // z^2
    float tau;
    if (z2 < 0.0625f) {                            // z < 0.25 (always, this data)
        tau = 1.0f + z2 * (-0.33333334f + z2 * (0.13333334f - z2 * 0.053968254f));
    } else {
        float vn = sv2 * frsq(fmaxf(sv2, 1e-28f));
        float z  = SQC * vn;
        float t  = fexp2(z * 2.8853901f);          // e^{2z}
        tau = (t - 1.0f) * frcp((t + 1.0f) * z);
    }
    float tn2 = tau * tau * sv2;                   // |t|^2 before project
    float ts  = tau;
    if (tn2 > MAXN2) ts = tau * (MAXN * frsq(tn2));  // project(t), rare
    float y2  = ts * ts * sv2;
    float xy  = ts * (P * qv);
    float x2  = a2;
    float A   = 1.0f + 2.0f * CC * xy + CC * y2;
    float B   = 1.0f - CC * x2;
    float den = fmaxf(1.0f + 2.0f * CC * xy + CC * CC * x2 * y2, MINN);
    float inv = frcp(den);
    float n2  = (A * A * x2 + 2.0f * A * B * xy + B * B * y2) * (inv * inv);
    float ps  = 1.0f;
    if (n2 > MAXN2) ps = MAXN * frsq(fmaxf(n2, 1e-28f));  // project(acc'), rare
    a2 = ps * ps * n2;
    return make_float2(A * inv * ps, B * inv * ps * ts);
}

__device__ __forceinline__ float2 final_scalars(float sacc, float a2, float bh) {
    float y2  = 4096.0f * bh * bh;
    float xy  = bh * sacc;
    float x2  = a2;
    float A   = 1.0f + 2.0f * CC * xy + CC * y2;
    float B   = 1.0f - CC * x2;
    float den = fmaxf(1.0f + 2.0f * CC * xy + CC * CC * x2 * y2, MINN);
    float inv = frcp(den);
    float n2  = (A * A * x2 + 2.0f * A * B * xy + B * B * y2) * (inv * inv);
    float ps  = 1.0f;
    if (n2 > MAXN2) ps = MAXN * frsq(fmaxf(n2, 1e-28f));
    return make_float2(A * inv * ps, B * inv * ps * bh);
}

// MOV-free window row: 3 vector LDS from the dual-copy tile.
// pA 16B-aligned; shifted copy at pA+TSZ.
// row[0],row[2] from LDS.128(A); row[4] from LDS.64(A+4); row[1],row[3] from LDS.128(B).
__device__ __forceinline__ void loadrow(const float* pA, u64* row) {
    ulonglong2 a = *(const ulonglong2*)pA;          // (p0, p2)
    ulonglong2 bsh = *(const ulonglong2*)(pA + TSZ);// (p1, p3)
    u64 p4 = *(const u64*)(pA + 4);                 // p4
    row[0] = a.x;  row[1] = bsh.x;  row[2] = a.y;  row[3] = bsh.y;  row[4] = p4;
}

// ---------------------------------------------------------------------------
// Kernel 2: one CTA per (b, channel pair) — exact R14 structure (best: 774us)
// with ONE change: dual-copy tile => MOV-free window loads (3 LDS, 0 MOV
// per row vs 2 LDS + 5 MOV). Double-buffered tile pairs in dynamic smem.
// ---------------------------------------------------------------------------
__global__ __launch_bounds__(256, 2)
void main_kernel(const float* __restrict__ w, float* __restrict__ out) {
    const int b    = blockIdx.y;
    const int c0   = blockIdx.x * 2;
    const int tid  = threadIdx.x;
    const int ty   = tid >> 4;
    const int tx   = tid & 15;
    const int lane = tid & 31;
    const int wid  = tid >> 5;
    const int par  = lane & 1;          // my scalar-chain channel (0 or 1)

    extern __shared__ float su[];       // 2 tile pairs (2*35904B dynamic)
    __shared__ u64    swp[2][576];      // weights pre-duplicated (w,w)
    __shared__ float2 sred[2][16];      // [buf][wid*2 + parity]

    for (int i = tid; i < 1152; i += 256) {
        int cc = i / 576, rem = i - cc * 576;
        float wv = w[(size_t)(c0 + cc) * 576 + rem];
        swp[cc][rem] = pk(wv, wv);
    }

    const unsigned su_s = (unsigned)__cvta_generic_to_shared(su);
    const float4* gbase = (const float4*)(g_u + (size_t)(b * 64) * PSZ);
    const int tail = tid + 2048;            // only first 196 threads copy chunk 9

    // preload tile pair 0 into buf0 via cp.async
    #pragma unroll
    for (int k = 0; k < 8; k++) {
        int i = tid + (k << 8);
        cpasync16(su_s + i * 16, gbase + i);
    }
    if (tail < PSZ4) cpasync16(su_s + tail * 16, gbase + tail);
    CP_COMMIT();
    CP_WAIT0();
    __syncthreads();

    u64 q0a[8], q1a[8];                 // acc = P * q, packed col pairs
    #pragma unroll
    for (int i = 0; i < 8; i++) { q0a[i] = 0ull; q1a[i] = 0ull; }
    float a2m = 0.0f, Pm = 1.0f;        // per-lane: channel `par`'s scan state

    const int baseoff = (4 * ty) * TW + 4 * tx;

    #pragma unroll 2
    for (int j = 0; j < 64; j++) {
        const int cur = j & 1;

        // ---- branchless async prefetch of tile pair (j+1)&63 ----
        {
            const float4* gn = gbase + (size_t)((j + 1) & 63) * PSZ4;
            unsigned sn = su_s + (cur ^ 1) * PAIRB;
            #pragma unroll
            for (int k = 0; k < 8; k++) {
                int i = tid + (k << 8);
                cpasync16(sn + i * 16, gn + i);
            }
            if (tail < PSZ4) cpasync16(sn + tail * 16, gn + tail);
            CP_COMMIT();
        }

        const float* basep = su + cur * PSZ + baseoff;
        const u64* wp0 = &swp[0][j * 9];
        const u64* wp1 = &swp[1][j * 9];

        // ---- conv: row-streaming, MOV-free window loads ----
        u64 v0[8], v1[8];
        #pragma unroll
        for (int i = 0; i < 8; i++) { v0[i] = 0ull; v1[i] = 0ull; }

        #pragma unroll
        for (int dr = 0; dr < 6; dr++) {
            u64 row[5];
            loadrow(basep + dr * TW, row);
            const int orlo = (dr - 2 > 0) ? dr - 2 : 0;
            const int orhi = (dr < 3) ? dr : 3;
            #pragma unroll
            for (int orow = orlo; orow <= orhi; orow++) {
                const int r = dr - orow;
                #pragma unroll
                for (int k = 0; k < 3; k++) {
                    u64 wa = wp0[r * 3 + k];
                    u64 wb = wp1[r * 3 + k];
                    v0[orow * 2]     = fma2(row[k],     wa, v0[orow * 2]);
                    v0[orow * 2 + 1] = fma2(row[2 + k], wa, v0[orow * 2 + 1]);
                    v1[orow * 2]     = fma2(row[k],     wb, v1[orow * 2]);
                    v1[orow * 2 + 1] = fma2(row[2 + k], wb, v1[orow * 2 + 1]);
                }
            }
        }

        // ---- fused packed reduction: |v|^2 and <q,v> per channel ----
        u64 sq0 = 0ull, av0 = 0ull, sq1 = 0ull, av1 = 0ull;
        #pragma unroll
        for (int i = 0; i < 8; i++) {
            sq0 = fma2(v0[i], v0[i], sq0);
            av0 = fma2(q0a[i], v0[i], av0);
            sq1 = fma2(v1[i], v1[i], sq1);
            av1 = fma2(q1a[i], v1[i], av1);
        }
        float2 pa = unpk(sq0), pb = unpk(av0), pc = unpk(sq1), pd = unpk(av1);
        float s0p = pa.x + pa.y, d0p = pb.x + pb.y;   // ch0 partials
        float s1p = pc.x + pc.y, d1p = pd.x + pd.y;   // ch1 partials

        // ---- parity-split butterfly: even lanes own ch0, odd lanes ch1 ----
        float s_mine = par ? s1p : s0p;
        float d_mine = par ? d1p : d0p;
        float s_oth  = par ? s0p : s1p;
        float d_oth  = par ? d0p : d1p;
        s_mine += __shfl_xor_sync(0xffffffffu, s_oth, 1);
        d_mine += __shfl_xor_sync(0xffffffffu, d_oth, 1);
        #pragma unroll
        for (int o = 2; o <= 16; o <<= 1) {
            s_mine += __shfl_xor_sync(0xffffffffu, s_mine, o);
            d_mine += __shfl_xor_sync(0xffffffffu, d_mine, o);
        }
        if (lane < 2) sred[cur][wid * 2 + par] = make_float2(s_mine, d_mine);

        // prefetch must land before the barrier publishes the buffer
        CP_WAIT0();
        __syncthreads();                      // single barrier per scan step

        // tree-sum the 8 warp partials of MY parity (float2, broadcast reads)
        float2 r0 = sred[cur][0 * 2 + par], r1 = sred[cur][1 * 2 + par];
        float2 r2 = sred[cur][2 * 2 + par], r3 = sred[cur][3 * 2 + par];
        float2 r4 = sred[cur][4 * 2 + par], r5 = sred[cur][5 * 2 + par];
        float2 r6 = sred[cur][6 * 2 + par], r7 = sred[cur][7 * 2 + par];
        float sv2 = ((r0.x + r1.x) + (r2.x + r3.x)) + ((r4.x + r5.x) + (r6.x + r7.x));
        float qv  = ((r0.y + r1.y) + (r2.y + r3.y)) + ((r4.y + r5.y) + (r6.y + r7.y));

        // ---- lane-parity scalar chain ----
        float2 s = step_scalars(sv2, qv, Pm, a2m);
        Pm *= s.x;
        float qcm = s.y * frcp(Pm);
        float qc0 = __shfl_sync(0xffffffffu, qcm, 0);
        float qc1 = __shfl_sync(0xffffffffu, qcm, 1);
        u64 QC0 = pk(qc0, qc0), QC1 = pk(qc1, qc1);
        #pragma unroll
        for (int i = 0; i < 8; i++) {
            q0a[i] = fma2(QC0, v0[i], q0a[i]);
            q1a[i] = fma2(QC1, v1[i], q1a[i]);
        }
    }

    // ---- epilogue: mobius bias add + project (acc = P*q) ----
    float sa0 = 0.0f, sa1 = 0.0f;
    #pragma unroll
    for (int i = 0; i < 8; i++) {
        float2 p0 = unpk(q0a[i]); sa0 += p0.x + p0.y;
        float2 p1 = unpk(q1a[i]); sa1 += p1.x + p1.y;
    }
    {
        float m  = par ? sa1 : sa0;
        float ot = par ? sa0 : sa1;
        m += __shfl_xor_sync(0xffffffffu, ot, 1);
        #pragma unroll
        for (int o = 2; o <= 16; o <<= 1)
            m += __shfl_xor_sync(0xffffffffu, m, o);
        if (lane < 2) sred[0][wid * 2 + par] = make_float2(m, 0.f);
    }
    __syncthreads();
    float tm = 0.0f;
    #pragma unroll
    for (int i = 0; i < 8; i++) tm += sred[0][i * 2 + par].x;

    // lane-parity final scalars, then broadcast
    float2 f = final_scalars(Pm * tm, a2m, g_bh[c0 + par]);
    float fxm = f.x * Pm;
    float fa0 = __shfl_sync(0xffffffffu, fxm, 0);
    float fb0 = __shfl_sync(0xffffffffu, f.y, 0);
    float fa1 = __shfl_sync(0xffffffffu, fxm, 1);
    float fb1 = __shfl_sync(0xffffffffu, f.y, 1);
    u64 FA0 = pk(fa0, fa0), FB0 = pk(fb0, fb0);
    u64 FA1 = pk(fa1, fa1), FB1 = pk(fb1, fb1);

    u64* o0 = (u64*)(out + ((size_t)(b * 128 + c0)) * 4096);
    u64* o1 = o0 + 2048;
    #pragma unroll
    for (int orow = 0; orow < 4; orow++) {
        #pragma unroll
        for (int p = 0; p < 2; p++) {
            int pos = (4 * ty + orow) * 32 + 2 * tx + p;   // in float2 units
            o0[pos] = fma2(FA0, q0a[orow * 2 + p], FB0);
            o1[pos] = fma2(FA1, q1a[orow * 2 + p], FB1);
        }
    }
}

// ---------------------------------------------------------------------------
extern "C" void kernel_launch(void* const* d_in, const int* in_sizes, int n_in,
                              void* d_out, int out_size) {
    const float* x    = (const float*)d_in[0];   // [32,64,64,64]
    const float* wgt  = (const float*)d_in[1];   // [128,64,3,3]
    const float* bias = (const float*)d_in[2];   // [128]
    float* out = (float*)d_out;                  // [32,128,64,64]

    // opt-in for >48KB dynamic smem (host-side attribute, not a stream op)
    static int smem_set = 0;
    if (!smem_set) {
        cudaFuncSetAttribute(main_kernel,
                             cudaFuncAttributeMaxDynamicSharedMemorySize,
                             2 * PAIRB);
        smem_set = 1;
    }

    u_kernel<<<2049, 256>>>(x, bias);            // block 2048 also does bias
    dim3 grid(64, 32);                           // (cout/2, bs)
    main_kernel<<<grid, 256, 2 * PAIRB>>>(wgt, out);
}